// round 2
// baseline (speedup 1.0000x reference)
#include <cuda_runtime.h>
#include <cfloat>
#include <math.h>

#define BATCH 8
#define MPTS 512
#define P_TOT (BATCH*MPTS)        // 4096
#define DDIM 256
#define HH 480
#define WW 640
#define NMEM 50000
#define THR2 0.01f
#define EPSF 1e-8f

// NN kernel tiling
#define TB 128                    // threads per block
#define PT 8                      // points per thread
#define CH 128                    // mem points staged per chunk
#define NSLICE 74                 // 4 x 74 = 296 blocks = 2 per SM
#define SL 676                    // ceil(50000/74)
#define GRP 32                    // argmax tracking group

// ---- scratch (device globals; allocation-guard safe) ----
__device__ float               g_world[P_TOT*3];
__device__ int                 g_valid[P_TOT];
__device__ unsigned long long  g_bestKey[P_TOT];
__device__ int                 g_flag[P_TOT];     // 0 invalid, 1 unmatched, 2 matched
__device__ int                 g_widx[P_TOT];
__device__ int                 g_winner[NMEM];
__device__ float               g_partial[128];
__device__ int                 g_nvalid;
__device__ int                 g_nmatch;

// ---------------- helpers ----------------
__device__ __forceinline__ float nhn(float mx, float my, float mz){
    // -0.5*|m|^2 with pinned rounding (must match between stage & rescan)
    return -0.5f * __fmaf_rn(mz, mz, __fmaf_rn(my, my, __fmul_rn(mx, mx)));
}
__device__ __forceinline__ unsigned fkey(float f){
    unsigned u = __float_as_uint(f);
    return (u & 0x80000000u) ? ~u : (u | 0x80000000u);
}
__device__ __forceinline__ float unfkey(unsigned k){
    unsigned u = (k & 0x80000000u) ? (k & 0x7FFFFFFFu) : ~k;
    return __uint_as_float(u);
}

// ---------------- kernel 0: init ----------------
__global__ void k_init(){
    int i = blockIdx.x * blockDim.x + threadIdx.x;
    if (i < NMEM) g_winner[i] = -1;
}

// ---------------- kernel 1: pix2world ----------------
__global__ void __launch_bounds__(MPTS) k_pix2world(
        const float* __restrict__ pts2, const float* __restrict__ depth,
        const float* __restrict__ pose, const float* __restrict__ Kmat){
    int bb = blockIdx.x;
    int m  = threadIdx.x;
    __shared__ float Ki[9];
    __shared__ float Rt[12];
    if (m == 0){
        const float* K = Kmat + bb*9;
        float k00=K[0],k01=K[1],k02=K[2],k10=K[3],k11=K[4],k12=K[5],k20=K[6],k21=K[7],k22=K[8];
        float c00 =  (k11*k22 - k12*k21);
        float c01 = -(k10*k22 - k12*k20);
        float c02 =  (k10*k21 - k11*k20);
        float det = k00*c00 + k01*c01 + k02*c02;
        float inv = 1.0f/det;
        Ki[0]= c00*inv;  Ki[1]=-(k01*k22-k02*k21)*inv;  Ki[2]= (k01*k12-k02*k11)*inv;
        Ki[3]= c01*inv;  Ki[4]= (k00*k22-k02*k20)*inv;  Ki[5]=-(k00*k12-k02*k10)*inv;
        Ki[6]= c02*inv;  Ki[7]=-(k00*k21-k01*k20)*inv;  Ki[8]= (k00*k11-k01*k10)*inv;
    }
    if (m < 12) Rt[m] = pose[bb*12 + m];
    __syncthreads();

    int p = bb*MPTS + m;
    float u = pts2[p*2+0];
    float v = pts2[p*2+1];
    float uc = fminf(fmaxf(u, 0.0f), 638.999f);
    float vc = fminf(fmaxf(v, 0.0f), 478.999f);
    float u0 = floorf(uc), v0 = floorf(vc);
    float du = uc - u0,   dv = vc - v0;
    int iu = (int)u0, iv = (int)v0;
    const float* dp = depth + (size_t)bb*HH*WW;
    float d00 = dp[iv*WW + iu],       d01 = dp[iv*WW + iu + 1];
    float d10 = dp[(iv+1)*WW + iu],   d11 = dp[(iv+1)*WW + iu + 1];
    float d = d00*(1.0f-du)*(1.0f-dv) + d01*du*(1.0f-dv)
            + d10*(1.0f-du)*dv        + d11*du*dv;
    float cx = (Ki[0]*u + Ki[1]*v + Ki[2]) * d;
    float cy = (Ki[3]*u + Ki[4]*v + Ki[5]) * d;
    float cz = (Ki[6]*u + Ki[7]*v + Ki[8]) * d;
    float wx = Rt[0]*cx + Rt[1]*cy + Rt[2]*cz  + Rt[3];
    float wy = Rt[4]*cx + Rt[5]*cy + Rt[6]*cz  + Rt[7];
    float wz = Rt[8]*cx + Rt[9]*cy + Rt[10]*cz + Rt[11];
    bool vld = (d > 0.0f) && isfinite(wx) && isfinite(wy) && isfinite(wz);
    g_world[p*3+0] = vld ? wx : 1e6f;   // reference masks invalid pts to 1e6
    g_world[p*3+1] = vld ? wy : 1e6f;
    g_world[p*3+2] = vld ? wz : 1e6f;
    g_valid[p]   = vld ? 1 : 0;
    g_bestKey[p] = 0ULL;
}

// ---------------- kernel 2: NN argmax of (p.m - 0.5|m|^2) ----------------
__global__ void __launch_bounds__(TB) k_nn(const float* __restrict__ mem){
    __shared__ float4 sh[CH];          // {mx, my, mz, -0.5|m|^2}
    const int tid   = threadIdx.x;
    const int pbase = blockIdx.x * (TB*PT) + tid;
    const int s0    = blockIdx.y * SL;
    const int s1    = min(s0 + SL, NMEM);

    float px[PT], py[PT], pz[PT], smax[PT];
    int   bc[PT];
    #pragma unroll
    for (int k = 0; k < PT; k++){
        int p = pbase + k*TB;
        px[k] = g_world[p*3+0]; py[k] = g_world[p*3+1]; pz[k] = g_world[p*3+2];
        smax[k] = -FLT_MAX; bc[k] = s0;
    }

    for (int c0 = s0; c0 < s1; c0 += CH){
        const int cn = min(CH, s1 - c0);
        __syncthreads();
        if (tid < cn){
            int j = c0 + tid;
            float mx = mem[j*3+0], my = mem[j*3+1], mz = mem[j*3+2];
            sh[tid] = make_float4(mx, my, mz, nhn(mx, my, mz));
        }
        __syncthreads();
        for (int j0 = 0; j0 < cn; j0 += GRP){
            int je = min(j0 + GRP, cn);
            float old[PT];
            #pragma unroll
            for (int k = 0; k < PT; k++) old[k] = smax[k];
            #pragma unroll 8
            for (int j = j0; j < je; j++){
                float4 mm = sh[j];
                #pragma unroll
                for (int k = 0; k < PT; k++){
                    float s = __fmaf_rn(px[k], mm.x,
                              __fmaf_rn(py[k], mm.y,
                              __fmaf_rn(pz[k], mm.z, mm.w)));
                    smax[k] = fmaxf(smax[k], s);
                }
            }
            #pragma unroll
            for (int k = 0; k < PT; k++)
                if (smax[k] > old[k]) bc[k] = c0 + j0;  // group of first occurrence of final max
        }
    }

    // exact index via bit-identical rescan of the winning group
    #pragma unroll
    for (int k = 0; k < PT; k++){
        int p  = pbase + k*TB;
        int cb = bc[k];
        int ce = min(cb + GRP, s1);
        int idx = cb;
        bool fnd = false;
        for (int j = cb; j < ce; j++){
            float mx = mem[j*3+0], my = mem[j*3+1], mz = mem[j*3+2];
            float s = __fmaf_rn(px[k], mx,
                      __fmaf_rn(py[k], my,
                      __fmaf_rn(pz[k], mz, nhn(mx, my, mz))));
            if (!fnd && s == smax[k]){ idx = j; fnd = true; }
        }
        unsigned long long key = ((unsigned long long)fkey(smax[k]) << 32)
                               | (unsigned long long)(0xFFFFFFFFu - (unsigned)idx);
        atomicMax(&g_bestKey[p], key);
    }
}

// ---------------- kernel 3: decide match/unmatched + scan slots + winners ----
__global__ void __launch_bounds__(1024) k_decide(const int* __restrict__ next_ptr){
    __shared__ int sc[1024];
    const int t = threadIdx.x;

    int u_loc[4], m_loc[4], v_loc[4], idxv[4];
    int usum = 0, vsum = 0, msum = 0;
    #pragma unroll
    for (int i = 0; i < 4; i++){
        int p = t*4 + i;
        unsigned long long key = g_bestKey[p];
        int idx = (int)(0xFFFFFFFFu - (unsigned)(key & 0xFFFFFFFFull));
        float score = unfkey((unsigned)(key >> 32));
        float x = g_world[p*3+0], y = g_world[p*3+1], z = g_world[p*3+2];
        float pp = __fmaf_rn(z, z, __fmaf_rn(y, y, __fmul_rn(x, x)));
        float dmin = pp - 2.0f*score;
        int v = g_valid[p];
        int m = (dmin < THR2) && v;
        int u = (!m) && v;
        g_flag[p] = m ? 2 : (u ? 1 : 0);
        u_loc[i] = u; m_loc[i] = m; v_loc[i] = v; idxv[i] = idx;
        usum += u; vsum += v; msum += m;
    }

    // inclusive scan of per-thread unmatched counts (Hillis-Steele)
    sc[t] = usum; __syncthreads();
    for (int off = 1; off < 1024; off <<= 1){
        int val = (t >= off) ? sc[t - off] : 0;
        __syncthreads();
        sc[t] += val;
        __syncthreads();
    }
    int base = sc[t] - usum;     // exclusive prefix
    int np = next_ptr[0];

    int run = base;
    #pragma unroll
    for (int i = 0; i < 4; i++){
        int p = t*4 + i;
        int w;
        if (u_loc[i]){ w = (np + run) % NMEM; run++; }
        else         { w = idxv[i]; }
        g_widx[p] = w;
        // all points (incl. invalid) compete for last-writer-wins
        atomicMax(&g_winner[w], p);
        (void)m_loc; (void)v_loc;
    }

    // reductions: nvalid, nmatch (deterministic)
    __syncthreads();
    sc[t] = vsum; __syncthreads();
    for (int s = 512; s > 0; s >>= 1){ if (t < s) sc[t] += sc[t+s]; __syncthreads(); }
    if (t == 0) g_nvalid = sc[0];
    __syncthreads();
    sc[t] = msum; __syncthreads();
    for (int s = 512; s > 0; s >>= 1){ if (t < s) sc[t] += sc[t+s]; __syncthreads(); }
    if (t == 0) g_nmatch = sc[0];
}

// ---------------- kernel 4: loss dots (deterministic partials) -------------
__global__ void __launch_bounds__(256) k_loss(const float* __restrict__ desc,
                                              const float* __restrict__ memdesc){
    __shared__ float ws[8];
    const int wid  = threadIdx.x >> 5;
    const int lane = threadIdx.x & 31;
    const int wg   = blockIdx.x * 8 + wid;

    float acc = 0.0f;
    #pragma unroll
    for (int i = 0; i < 4; i++){
        int p = wg*4 + i;
        int v = g_valid[p];
        float c = 0.0f;
        if (v){
            int f = g_flag[p];
            const float* a = desc + (size_t)p * DDIM;
            float na = 0.0f;
            if (f == 2){
                int idx = g_widx[p];   // == argmin idx for matched points
                const float* b = memdesc + (size_t)idx * DDIM;
                float nb = 0.0f, dt = 0.0f;
                #pragma unroll
                for (int e = lane; e < DDIM; e += 32){
                    float av = a[e], bv = b[e];
                    na += av*av; nb += bv*bv; dt += av*bv;
                }
                #pragma unroll
                for (int o = 16; o > 0; o >>= 1){
                    na += __shfl_xor_sync(0xFFFFFFFFu, na, o);
                    nb += __shfl_xor_sync(0xFFFFFFFFu, nb, o);
                    dt += __shfl_xor_sync(0xFFFFFFFFu, dt, o);
                }
                float n1 = fmaxf(sqrtf(na), EPSF);
                float n2 = fmaxf(sqrtf(nb), EPSF);
                c = dt / (n1 * n2);
            } else {
                #pragma unroll
                for (int e = lane; e < DDIM; e += 32){
                    float av = a[e]; na += av*av;
                }
                #pragma unroll
                for (int o = 16; o > 0; o >>= 1)
                    na += __shfl_xor_sync(0xFFFFFFFFu, na, o);
                float n1 = fmaxf(sqrtf(na), EPSF);
                c = na / (n1 * n1);     // cos(a, a) with ref's max(norm,eps)
            }
        }
        acc += c;
    }
    if (lane == 0) ws[wid] = acc;
    __syncthreads();
    if (threadIdx.x == 0){
        float s = 0.0f;
        #pragma unroll
        for (int i = 0; i < 8; i++) s += ws[i];
        g_partial[blockIdx.x] = s;
    }
}

// ---------------- kernel 5: patch winning rows over the bulk copy ----------
__global__ void __launch_bounds__(256) k_patch(const float* __restrict__ desc,
                                               const float* __restrict__ memdesc,
                                               float* __restrict__ out){
    const int wid  = threadIdx.x >> 5;
    const int lane = threadIdx.x & 31;
    const int p    = blockIdx.x * 8 + wid;
    if (p >= P_TOT) return;
    int f = g_flag[p];
    if (f == 0) return;                      // invalid: value no-op
    int r = g_widx[p];
    if (g_winner[r] != p) return;            // not the last writer

    float* opts  = out + 2;
    float* odesc = out + 2 + NMEM*3;

    if (f == 1){ // unmatched: raw insert
        if (lane < 3) opts[r*3 + lane] = g_world[p*3 + lane];
        const float2* s = (const float2*)(desc + (size_t)p * DDIM);
        float2*       d = (float2*)(odesc + (size_t)r * DDIM);
        #pragma unroll
        for (int e = lane; e < DDIM/2; e += 32) d[e] = s[e];
    } else {     // matched: EMA + renormalize (pts stay original, already copied)
        const float* od = memdesc + (size_t)r * DDIM;
        const float* nd = desc    + (size_t)p * DDIM;
        float u[8]; float ss = 0.0f;
        #pragma unroll
        for (int i = 0; i < 8; i++){
            int e = lane + 32*i;
            float x = od[e]*0.5f + nd[e]*0.5f;
            u[i] = x; ss += x*x;
        }
        #pragma unroll
        for (int o = 16; o > 0; o >>= 1)
            ss += __shfl_xor_sync(0xFFFFFFFFu, ss, o);
        float inv = 1.0f / (sqrtf(ss) + EPSF);
        #pragma unroll
        for (int i = 0; i < 8; i++){
            int e = lane + 32*i;
            odesc[(size_t)r * DDIM + e] = u[i] * inv;
        }
    }
}

// ---------------- kernel 6: finalize loss + n_match ------------------------
__global__ void k_final(float* __restrict__ out){
    if (threadIdx.x == 0){
        float s = 0.0f;
        for (int i = 0; i < 128; i++) s += g_partial[i];
        int nv = g_nvalid; if (nv < 1) nv = 1;
        out[0] = 1.0f - s / (float)nv;
        out[1] = (float)g_nmatch;
    }
}

// ---------------- launch ----------------
extern "C" void kernel_launch(void* const* d_in, const int* in_sizes, int n_in,
                              void* d_out, int out_size) {
    const float* points   = (const float*)d_in[0];
    const float* depth    = (const float*)d_in[1];
    const float* pose     = (const float*)d_in[2];
    const float* Kmat     = (const float*)d_in[3];
    const float* desc     = (const float*)d_in[4];
    const float* mem_pts  = (const float*)d_in[5];
    const float* mem_desc = (const float*)d_in[6];
    const int*   next_ptr = (const int*)d_in[7];
    float* out = (float*)d_out;

    k_init<<<(NMEM + 255)/256, 256>>>();
    k_pix2world<<<BATCH, MPTS>>>(points, depth, pose, Kmat);
    k_nn<<<dim3(P_TOT/(TB*PT), NSLICE), TB>>>(mem_pts);
    k_decide<<<1, 1024>>>(next_ptr);
    k_loss<<<128, 256>>>(desc, mem_desc);
    cudaMemcpyAsync(out + 2,           mem_pts,  (size_t)NMEM*3*sizeof(float),
                    cudaMemcpyDeviceToDevice, 0);
    cudaMemcpyAsync(out + 2 + NMEM*3,  mem_desc, (size_t)NMEM*DDIM*sizeof(float),
                    cudaMemcpyDeviceToDevice, 0);
    k_patch<<<P_TOT/8, 256>>>(desc, mem_desc, out);
    k_final<<<1, 32>>>(out);
}

// round 3
// speedup vs baseline: 1.2238x; 1.2238x over previous
#include <cuda_runtime.h>
#include <cfloat>
#include <math.h>

#define BATCH 8
#define MPTS 512
#define P_TOT (BATCH*MPTS)        // 4096
#define DDIM 256
#define HH 480
#define WW 640
#define NMEM 50000
#define THR2 0.01f
#define EPSF 1e-8f

// NN kernel tiling
#define TB 256                    // threads per block
#define PT 8                      // points per thread
#define CH 256                    // mem points staged per chunk (128 pairs)
#define NSLICE 148                // 2 x 148 = 296 blocks = 2 per SM
#define SL 338                    // ceil(50000/148)
#define GRP 32                    // argmax tracking group (mem points)

#define ROW_BLOCKS 6250           // 6250*8 = 50000 rows
#define LOSS_BLOCKS 128

// ---- scratch (device globals; allocation-guard safe) ----
__device__ float               g_world[P_TOT*3];
__device__ int                 g_valid[P_TOT];
__device__ unsigned long long  g_bestKey[P_TOT];
__device__ int                 g_flag[P_TOT];     // 0 invalid, 1 unmatched, 2 matched
__device__ int                 g_widx[P_TOT];
__device__ int                 g_winner[NMEM];    // stores p+1; 0 = none (zero-init, restored by k_final)
__device__ float               g_partial[LOSS_BLOCKS];
__device__ int                 g_nvalid;
__device__ int                 g_nmatch;

// ---------------- helpers ----------------
__device__ __forceinline__ float nhn(float mx, float my, float mz){
    // -0.5*|m|^2 with pinned rounding (must match between stage & rescan)
    return -0.5f * __fmaf_rn(mz, mz, __fmaf_rn(my, my, __fmul_rn(mx, mx)));
}
__device__ __forceinline__ unsigned fkey(float f){
    unsigned u = __float_as_uint(f);
    return (u & 0x80000000u) ? ~u : (u | 0x80000000u);
}
__device__ __forceinline__ float unfkey(unsigned k){
    unsigned u = (k & 0x80000000u) ? (k & 0x7FFFFFFFu) : ~k;
    return __uint_as_float(u);
}
__device__ __forceinline__ unsigned long long pk2(float lo, float hi){
    unsigned long long r;
    asm("mov.b64 %0, {%1, %2};" : "=l"(r) : "r"(__float_as_uint(lo)), "r"(__float_as_uint(hi)));
    return r;
}
__device__ __forceinline__ void upk2(unsigned long long v, float& lo, float& hi){
    unsigned a, b;
    asm("mov.b64 {%0, %1}, %2;" : "=r"(a), "=r"(b) : "l"(v));
    lo = __uint_as_float(a); hi = __uint_as_float(b);
}
__device__ __forceinline__ unsigned long long fma2(unsigned long long a, unsigned long long b,
                                                   unsigned long long c){
    unsigned long long d;
    asm("fma.rn.f32x2 %0, %1, %2, %3;" : "=l"(d) : "l"(a), "l"(b), "l"(c));
    return d;
}

// ---------------- kernel 1: pix2world ----------------
__global__ void __launch_bounds__(MPTS) k_pix2world(
        const float* __restrict__ pts2, const float* __restrict__ depth,
        const float* __restrict__ pose, const float* __restrict__ Kmat){
    int bb = blockIdx.x;
    int m  = threadIdx.x;
    __shared__ float Ki[9];
    __shared__ float Rt[12];
    if (m == 0){
        const float* K = Kmat + bb*9;
        float k00=K[0],k01=K[1],k02=K[2],k10=K[3],k11=K[4],k12=K[5],k20=K[6],k21=K[7],k22=K[8];
        float c00 =  (k11*k22 - k12*k21);
        float c01 = -(k10*k22 - k12*k20);
        float c02 =  (k10*k21 - k11*k20);
        float det = k00*c00 + k01*c01 + k02*c02;
        float inv = 1.0f/det;
        Ki[0]= c00*inv;  Ki[1]=-(k01*k22-k02*k21)*inv;  Ki[2]= (k01*k12-k02*k11)*inv;
        Ki[3]= c01*inv;  Ki[4]= (k00*k22-k02*k20)*inv;  Ki[5]=-(k00*k12-k02*k10)*inv;
        Ki[6]= c02*inv;  Ki[7]=-(k00*k21-k01*k20)*inv;  Ki[8]= (k00*k11-k01*k10)*inv;
    }
    if (m < 12) Rt[m] = pose[bb*12 + m];
    __syncthreads();

    int p = bb*MPTS + m;
    float u = pts2[p*2+0];
    float v = pts2[p*2+1];
    float uc = fminf(fmaxf(u, 0.0f), 638.999f);
    float vc = fminf(fmaxf(v, 0.0f), 478.999f);
    float u0 = floorf(uc), v0 = floorf(vc);
    float du = uc - u0,   dv = vc - v0;
    int iu = (int)u0, iv = (int)v0;
    const float* dp = depth + (size_t)bb*HH*WW;
    float d00 = dp[iv*WW + iu],       d01 = dp[iv*WW + iu + 1];
    float d10 = dp[(iv+1)*WW + iu],   d11 = dp[(iv+1)*WW + iu + 1];
    float d = d00*(1.0f-du)*(1.0f-dv) + d01*du*(1.0f-dv)
            + d10*(1.0f-du)*dv        + d11*du*dv;
    float cx = (Ki[0]*u + Ki[1]*v + Ki[2]) * d;
    float cy = (Ki[3]*u + Ki[4]*v + Ki[5]) * d;
    float cz = (Ki[6]*u + Ki[7]*v + Ki[8]) * d;
    float wx = Rt[0]*cx + Rt[1]*cy + Rt[2]*cz  + Rt[3];
    float wy = Rt[4]*cx + Rt[5]*cy + Rt[6]*cz  + Rt[7];
    float wz = Rt[8]*cx + Rt[9]*cy + Rt[10]*cz + Rt[11];
    bool vld = (d > 0.0f) && isfinite(wx) && isfinite(wy) && isfinite(wz);
    g_world[p*3+0] = vld ? wx : 1e6f;   // reference masks invalid pts to 1e6
    g_world[p*3+1] = vld ? wy : 1e6f;
    g_world[p*3+2] = vld ? wz : 1e6f;
    g_valid[p]   = vld ? 1 : 0;
    g_bestKey[p] = 0ULL;
}

// ---------------- kernel 2: NN argmax of (p.m - 0.5|m|^2), packed f32x2 -----
__global__ void __launch_bounds__(TB, 2) k_nn(const float* __restrict__ mem){
    __shared__ ulonglong2 sh[CH];      // per pair q: sh[2q]={mxx,myy}, sh[2q+1]={mzz,cc}
    const int tid   = threadIdx.x;
    const int pbase = blockIdx.x * (TB*PT) + tid;
    const int s0    = blockIdx.y * SL;
    const int s1    = min(s0 + SL, NMEM);

    unsigned long long pxx[PT], pyy[PT], pzz[PT];
    float smax[PT]; int bc[PT];
    #pragma unroll
    for (int k = 0; k < PT; k++){
        int p = pbase + k*TB;
        float x = g_world[p*3+0], y = g_world[p*3+1], z = g_world[p*3+2];
        pxx[k] = pk2(x, x); pyy[k] = pk2(y, y); pzz[k] = pk2(z, z);
        smax[k] = -FLT_MAX; bc[k] = s0;
    }

    for (int c0 = s0; c0 < s1; c0 += CH){
        const int cn  = min(CH, s1 - c0);
        const int np2 = (cn + 1) >> 1;
        __syncthreads();
        if (tid < np2){
            int i0 = c0 + 2*tid;
            int i1 = min(i0 + 1, s1 - 1);        // pad odd tail with duplicate
            float ax = mem[i0*3+0], ay = mem[i0*3+1], az = mem[i0*3+2];
            float bx = mem[i1*3+0], by = mem[i1*3+1], bz = mem[i1*3+2];
            sh[2*tid+0] = make_ulonglong2(pk2(ax,bx), pk2(ay,by));
            sh[2*tid+1] = make_ulonglong2(pk2(az,bz), pk2(nhn(ax,ay,az), nhn(bx,by,bz)));
        }
        __syncthreads();
        for (int j0 = 0; j0 < np2; j0 += GRP/2){
            int je = min(j0 + GRP/2, np2);
            float old[PT];
            #pragma unroll
            for (int k = 0; k < PT; k++) old[k] = smax[k];
            #pragma unroll 4
            for (int j = j0; j < je; j++){
                ulonglong2 t0 = sh[2*j+0];
                ulonglong2 t1 = sh[2*j+1];
                #pragma unroll
                for (int k = 0; k < PT; k++){
                    unsigned long long s2 =
                        fma2(pxx[k], t0.x, fma2(pyy[k], t0.y, fma2(pzz[k], t1.x, t1.y)));
                    float lo, hi; upk2(s2, lo, hi);
                    smax[k] = fmaxf(smax[k], lo);
                    smax[k] = fmaxf(smax[k], hi);
                }
            }
            #pragma unroll
            for (int k = 0; k < PT; k++)
                if (smax[k] > old[k]) bc[k] = c0 + 2*j0;   // group of first occurrence
        }
    }

    // exact index via bit-identical rescan of the winning 32-mem group
    #pragma unroll
    for (int k = 0; k < PT; k++){
        int p = pbase + k*TB;
        float px, py_, pz;
        { float dum; upk2(pxx[k], px, dum); upk2(pyy[k], py_, dum); upk2(pzz[k], pz, dum); }
        int cb = bc[k];
        int ce = min(cb + GRP, s1);
        int idx = cb;
        bool fnd = false;
        for (int j = cb; j < ce; j++){
            float mx = mem[j*3+0], my = mem[j*3+1], mz = mem[j*3+2];
            float s = __fmaf_rn(px, mx,
                      __fmaf_rn(py_, my,
                      __fmaf_rn(pz, mz, nhn(mx, my, mz))));
            if (!fnd && s == smax[k]){ idx = j; fnd = true; }
        }
        unsigned long long key = ((unsigned long long)fkey(smax[k]) << 32)
                               | (unsigned long long)(0xFFFFFFFFu - (unsigned)idx);
        atomicMax(&g_bestKey[p], key);
    }
}

// ---------------- kernel 3: decide + warp-scan slots + winners --------------
__global__ void __launch_bounds__(1024) k_decide(const int* __restrict__ next_ptr){
    __shared__ int sWarp[32];
    __shared__ int sExc[32];
    __shared__ int sV[32];
    __shared__ int sM[32];
    const int t = threadIdx.x, lane = t & 31, wid = t >> 5;

    int u4[4], idx4[4];
    int usum = 0, vsum = 0, msum = 0;
    #pragma unroll
    for (int i = 0; i < 4; i++){
        int p = t*4 + i;
        unsigned long long key = g_bestKey[p];
        int idx = (int)(0xFFFFFFFFu - (unsigned)(key & 0xFFFFFFFFull));
        float score = unfkey((unsigned)(key >> 32));
        float x = g_world[p*3+0], y = g_world[p*3+1], z = g_world[p*3+2];
        float pp = __fmaf_rn(z, z, __fmaf_rn(y, y, __fmul_rn(x, x)));
        float dmin = pp - 2.0f*score;
        int v = g_valid[p];
        int m = (dmin < THR2) && v;
        int u = v && !m;
        g_flag[p] = m ? 2 : (u ? 1 : 0);
        u4[i] = u; idx4[i] = idx;
        usum += u; vsum += v; msum += m;
    }

    // warp-level inclusive scan of per-thread unmatched counts
    int inc = usum;
    #pragma unroll
    for (int off = 1; off < 32; off <<= 1){
        int y = __shfl_up_sync(0xFFFFFFFFu, inc, off);
        if (lane >= off) inc += y;
    }
    if (lane == 31) sWarp[wid] = inc;
    __syncthreads();
    if (wid == 0){
        int v = sWarp[lane];
        int inc2 = v;
        #pragma unroll
        for (int off = 1; off < 32; off <<= 1){
            int y = __shfl_up_sync(0xFFFFFFFFu, inc2, off);
            if (lane >= off) inc2 += y;
        }
        sExc[lane] = inc2 - v;
    }
    __syncthreads();
    int base = sExc[wid] + (inc - usum);   // global exclusive prefix
    int np = next_ptr[0];

    int run = base;
    #pragma unroll
    for (int i = 0; i < 4; i++){
        int p = t*4 + i;
        int w;
        if (u4[i]){ w = (np + run) % NMEM; run++; }
        else      { w = idx4[i]; }
        g_widx[p] = w;
        atomicMax(&g_winner[w], p + 1);   // all points (incl. invalid) compete
    }

    // deterministic reductions
    #pragma unroll
    for (int off = 16; off > 0; off >>= 1){
        vsum += __shfl_xor_sync(0xFFFFFFFFu, vsum, off);
        msum += __shfl_xor_sync(0xFFFFFFFFu, msum, off);
    }
    if (lane == 0){ sV[wid] = vsum; sM[wid] = msum; }
    __syncthreads();
    if (wid == 0){
        int a = sV[lane], b = sM[lane];
        #pragma unroll
        for (int off = 16; off > 0; off >>= 1){
            a += __shfl_xor_sync(0xFFFFFFFFu, a, off);
            b += __shfl_xor_sync(0xFFFFFFFFu, b, off);
        }
        if (lane == 0){ g_nvalid = a; g_nmatch = b; }
    }
}

// ---------------- kernel 4: fused copy+patch (rows) and loss (points) -------
__global__ void __launch_bounds__(256) k_copyPatch(const float* __restrict__ desc,
                                                   const float* __restrict__ mem_pts,
                                                   const float* __restrict__ mem_desc,
                                                   float* __restrict__ out){
    const int wid  = threadIdx.x >> 5;
    const int lane = threadIdx.x & 31;
    float* opts  = out + 2;
    float* odesc = out + 2 + NMEM*3;

    if (blockIdx.x < ROW_BLOCKS){
        const int r = blockIdx.x * 8 + wid;    // memory row
        int w = g_winner[r];
        int mode = 0, p = -1;
        if (w > 0){ p = w - 1; mode = g_flag[p]; }

        // points
        if (lane < 3)
            opts[r*3 + lane] = (mode == 1) ? g_world[p*3 + lane] : mem_pts[r*3 + lane];

        float2* drow = (float2*)(odesc + (size_t)r * DDIM);   // 8B aligned
        if (mode == 1){
            // unmatched insert: raw descriptor
            const float4* s = (const float4*)(desc + (size_t)p * DDIM);
            float4 a0 = s[lane], a1 = s[lane + 32];
            drow[2*lane + 0]        = make_float2(a0.x, a0.y);
            drow[2*lane + 1]        = make_float2(a0.z, a0.w);
            drow[2*(lane+32) + 0]   = make_float2(a1.x, a1.y);
            drow[2*(lane+32) + 1]   = make_float2(a1.z, a1.w);
        } else if (mode == 2){
            // matched: EMA + renormalize
            const float4* b = (const float4*)(mem_desc + (size_t)r * DDIM);
            const float4* a = (const float4*)(desc     + (size_t)p * DDIM);
            float4 a0 = a[lane], a1 = a[lane+32];
            float4 b0 = b[lane], b1 = b[lane+32];
            float4 u0, u1;
            u0.x = a0.x*0.5f + b0.x*0.5f;  u0.y = a0.y*0.5f + b0.y*0.5f;
            u0.z = a0.z*0.5f + b0.z*0.5f;  u0.w = a0.w*0.5f + b0.w*0.5f;
            u1.x = a1.x*0.5f + b1.x*0.5f;  u1.y = a1.y*0.5f + b1.y*0.5f;
            u1.z = a1.z*0.5f + b1.z*0.5f;  u1.w = a1.w*0.5f + b1.w*0.5f;
            float ss = u0.x*u0.x + u0.y*u0.y + u0.z*u0.z + u0.w*u0.w
                     + u1.x*u1.x + u1.y*u1.y + u1.z*u1.z + u1.w*u1.w;
            #pragma unroll
            for (int o = 16; o > 0; o >>= 1)
                ss += __shfl_xor_sync(0xFFFFFFFFu, ss, o);
            float inv = 1.0f / (sqrtf(ss) + EPSF);
            drow[2*lane + 0]      = make_float2(u0.x*inv, u0.y*inv);
            drow[2*lane + 1]      = make_float2(u0.z*inv, u0.w*inv);
            drow[2*(lane+32) + 0] = make_float2(u1.x*inv, u1.y*inv);
            drow[2*(lane+32) + 1] = make_float2(u1.z*inv, u1.w*inv);
        } else {
            // untouched (or invalid winner): plain copy
            const float4* b = (const float4*)(mem_desc + (size_t)r * DDIM);
            float4 b0 = b[lane], b1 = b[lane + 32];
            drow[2*lane + 0]      = make_float2(b0.x, b0.y);
            drow[2*lane + 1]      = make_float2(b0.z, b0.w);
            drow[2*(lane+32) + 0] = make_float2(b1.x, b1.y);
            drow[2*(lane+32) + 1] = make_float2(b1.z, b1.w);
        }
    } else {
        // ---- loss blocks ----
        __shared__ float ws[8];
        const int lb = blockIdx.x - ROW_BLOCKS;   // 0..127
        const int wg = lb * 8 + wid;
        float acc = 0.0f;
        #pragma unroll
        for (int i = 0; i < 4; i++){
            int p = wg*4 + i;
            int v = g_valid[p];
            float c = 0.0f;
            if (v){
                int f = g_flag[p];
                const float4* a = (const float4*)(desc + (size_t)p * DDIM);
                float4 a0 = a[lane], a1 = a[lane+32];
                float na = a0.x*a0.x + a0.y*a0.y + a0.z*a0.z + a0.w*a0.w
                         + a1.x*a1.x + a1.y*a1.y + a1.z*a1.z + a1.w*a1.w;
                if (f == 2){
                    int idx = g_widx[p];
                    const float4* b = (const float4*)(mem_desc + (size_t)idx * DDIM);
                    float4 b0 = b[lane], b1 = b[lane+32];
                    float nb = b0.x*b0.x + b0.y*b0.y + b0.z*b0.z + b0.w*b0.w
                             + b1.x*b1.x + b1.y*b1.y + b1.z*b1.z + b1.w*b1.w;
                    float dt = a0.x*b0.x + a0.y*b0.y + a0.z*b0.z + a0.w*b0.w
                             + a1.x*b1.x + a1.y*b1.y + a1.z*b1.z + a1.w*b1.w;
                    #pragma unroll
                    for (int o = 16; o > 0; o >>= 1){
                        na += __shfl_xor_sync(0xFFFFFFFFu, na, o);
                        nb += __shfl_xor_sync(0xFFFFFFFFu, nb, o);
                        dt += __shfl_xor_sync(0xFFFFFFFFu, dt, o);
                    }
                    float n1 = fmaxf(sqrtf(na), EPSF);
                    float n2 = fmaxf(sqrtf(nb), EPSF);
                    c = dt / (n1 * n2);
                } else {
                    #pragma unroll
                    for (int o = 16; o > 0; o >>= 1)
                        na += __shfl_xor_sync(0xFFFFFFFFu, na, o);
                    float n1 = fmaxf(sqrtf(na), EPSF);
                    c = na / (n1 * n1);
                }
            }
            acc += c;
        }
        if (lane == 0) ws[wid] = acc;
        __syncthreads();
        if (threadIdx.x == 0){
            float s = 0.0f;
            #pragma unroll
            for (int i = 0; i < 8; i++) s += ws[i];
            g_partial[lb] = s;
        }
    }
}

// ---------------- kernel 5: finalize + restore winner array -----------------
__global__ void __launch_bounds__(128) k_final(float* __restrict__ out){
    __shared__ float s[128];
    const int t = threadIdx.x;
    s[t] = g_partial[t];
    __syncthreads();
    #pragma unroll
    for (int st = 64; st > 0; st >>= 1){
        if (t < st) s[t] += s[t + st];
        __syncthreads();
    }
    if (t == 0){
        int nv = g_nvalid; if (nv < 1) nv = 1;
        out[0] = 1.0f - s[0] / (float)nv;
        out[1] = (float)g_nmatch;
    }
    // restore g_winner to all-zero for the next (graph replay) invocation
    for (int i = t; i < P_TOT; i += 128)
        g_winner[g_widx[i]] = 0;
}

// ---------------- launch ----------------
extern "C" void kernel_launch(void* const* d_in, const int* in_sizes, int n_in,
                              void* d_out, int out_size) {
    const float* points   = (const float*)d_in[0];
    const float* depth    = (const float*)d_in[1];
    const float* pose     = (const float*)d_in[2];
    const float* Kmat     = (const float*)d_in[3];
    const float* desc     = (const float*)d_in[4];
    const float* mem_pts  = (const float*)d_in[5];
    const float* mem_desc = (const float*)d_in[6];
    const int*   next_ptr = (const int*)d_in[7];
    float* out = (float*)d_out;

    k_pix2world<<<BATCH, MPTS>>>(points, depth, pose, Kmat);
    k_nn<<<dim3(P_TOT/(TB*PT), NSLICE), TB>>>(mem_pts);
    k_decide<<<1, 1024>>>(next_ptr);
    k_copyPatch<<<ROW_BLOCKS + LOSS_BLOCKS, 256>>>(desc, mem_pts, mem_desc, out);
    k_final<<<1, 128>>>(out);
}

// round 4
// speedup vs baseline: 2.2211x; 1.8150x over previous
#include <cuda_runtime.h>
#include <cfloat>
#include <math.h>

#define BATCH 8
#define MPTS 512
#define P_TOT (BATCH*MPTS)        // 4096
#define DDIM 256
#define HH 480
#define WW 640
#define NMEM 50000
#define THR2 0.01f
#define EPSF 1e-8f

// spatial grid
#define GD 16                     // 16^3 = 4096 cells
#define NCELL (GD*GD*GD)
#define OX (-8.0f)
#define CS 1.0f

#define COPY_BLOCKS 1664
#define CNT_BLOCKS 224
#define CNT_THREADS (CNT_BLOCKS*256)
#define PL_BLOCKS 512             // patch+loss: 8 warps/block, warp per point

// ---- scratch (device globals; allocation-guard safe) ----
__device__ float               g_world[P_TOT*3];
__device__ int                 g_valid[P_TOT];
__device__ unsigned long long  g_bestKey[P_TOT];
__device__ int                 g_flag[P_TOT];     // 0 invalid, 1 unmatched, 2 matched
__device__ int                 g_widx[P_TOT];
__device__ int                 g_winner[NMEM];    // p+1; 0 = none (restored by k_final)
__device__ float               g_partial[PL_BLOCKS];
__device__ int                 g_nvalid;
__device__ int                 g_nmatch;
__device__ int                 g_cellCount[NCELL];      // zeroed statically + by k_final
__device__ int                 g_cellStart[NCELL+1];
__device__ int                 g_cursor[NCELL];
__device__ float4              g_tbl[NMEM];             // {x,y,z, idx-as-float-bits}

// ---------------- helpers ----------------
__device__ __forceinline__ int cellOf(float x){
    int c = (int)floorf((x - OX) * (1.0f/CS));
    return min(max(c, 0), GD-1);
}

// ---------------- node 1: bulk copy + histogram ----------------
__global__ void __launch_bounds__(256) k_prep(const float* __restrict__ mem_pts,
                                              const float* __restrict__ mem_desc,
                                              float* __restrict__ out){
    if (blockIdx.x < COPY_BLOCKS){
        // stream mem_desc (51.2 MB) -> out desc region (8B-aligned dst)
        int gid = blockIdx.x * 256 + threadIdx.x;
        const float4* s = (const float4*)mem_desc;
        float2* d = (float2*)(out + 2 + NMEM*3);
        const int n4 = NMEM*DDIM/4;
        for (int i = gid; i < n4; i += COPY_BLOCKS*256){
            float4 v = s[i];
            d[2*i+0] = make_float2(v.x, v.y);
            d[2*i+1] = make_float2(v.z, v.w);
        }
    } else {
        int k = (blockIdx.x - COPY_BLOCKS) * 256 + threadIdx.x;
        // copy mem_pts (600 KB)
        const float2* s2 = (const float2*)mem_pts;
        float2* d2 = (float2*)(out + 2);
        for (int j = k; j < NMEM*3/2; j += CNT_THREADS) d2[j] = s2[j];
        // cell histogram
        for (int i = k; i < NMEM; i += CNT_THREADS){
            int cx = cellOf(mem_pts[i*3+0]);
            int cy = cellOf(mem_pts[i*3+1]);
            int cz = cellOf(mem_pts[i*3+2]);
            atomicAdd(&g_cellCount[(cz*GD + cy)*GD + cx], 1);
        }
    }
}

// ---------------- node 2: pix2world (blocks 0-7) + cell scan (block 8) -----
__global__ void __launch_bounds__(1024) k_pix_scan(
        const float* __restrict__ pts2, const float* __restrict__ depth,
        const float* __restrict__ pose, const float* __restrict__ Kmat){
    if (blockIdx.x < BATCH){
        int bb = blockIdx.x;
        int m  = threadIdx.x;
        __shared__ float Ki[9];
        __shared__ float Rt[12];
        if (m == 0){
            const float* K = Kmat + bb*9;
            float k00=K[0],k01=K[1],k02=K[2],k10=K[3],k11=K[4],k12=K[5],k20=K[6],k21=K[7],k22=K[8];
            float c00 =  (k11*k22 - k12*k21);
            float c01 = -(k10*k22 - k12*k20);
            float c02 =  (k10*k21 - k11*k20);
            float det = k00*c00 + k01*c01 + k02*c02;
            float inv = 1.0f/det;
            Ki[0]= c00*inv;  Ki[1]=-(k01*k22-k02*k21)*inv;  Ki[2]= (k01*k12-k02*k11)*inv;
            Ki[3]= c01*inv;  Ki[4]= (k00*k22-k02*k20)*inv;  Ki[5]=-(k00*k12-k02*k10)*inv;
            Ki[6]= c02*inv;  Ki[7]=-(k00*k21-k01*k20)*inv;  Ki[8]= (k00*k11-k01*k10)*inv;
        }
        if (m < 12) Rt[m] = pose[bb*12 + m];
        __syncthreads();
        if (m >= MPTS) return;

        int p = bb*MPTS + m;
        float u = pts2[p*2+0];
        float v = pts2[p*2+1];
        float uc = fminf(fmaxf(u, 0.0f), 638.999f);
        float vc = fminf(fmaxf(v, 0.0f), 478.999f);
        float u0 = floorf(uc), v0 = floorf(vc);
        float du = uc - u0,   dv = vc - v0;
        int iu = (int)u0, iv = (int)v0;
        const float* dp = depth + (size_t)bb*HH*WW;
        float d00 = dp[iv*WW + iu],       d01 = dp[iv*WW + iu + 1];
        float d10 = dp[(iv+1)*WW + iu],   d11 = dp[(iv+1)*WW + iu + 1];
        float d = d00*(1.0f-du)*(1.0f-dv) + d01*du*(1.0f-dv)
                + d10*(1.0f-du)*dv        + d11*du*dv;
        float cx = (Ki[0]*u + Ki[1]*v + Ki[2]) * d;
        float cy = (Ki[3]*u + Ki[4]*v + Ki[5]) * d;
        float cz = (Ki[6]*u + Ki[7]*v + Ki[8]) * d;
        float wx = Rt[0]*cx + Rt[1]*cy + Rt[2]*cz  + Rt[3];
        float wy = Rt[4]*cx + Rt[5]*cy + Rt[6]*cz  + Rt[7];
        float wz = Rt[8]*cx + Rt[9]*cy + Rt[10]*cz + Rt[11];
        bool vld = (d > 0.0f) && isfinite(wx) && isfinite(wy) && isfinite(wz);
        g_world[p*3+0] = vld ? wx : 1e6f;
        g_world[p*3+1] = vld ? wy : 1e6f;
        g_world[p*3+2] = vld ? wz : 1e6f;
        g_valid[p]   = vld ? 1 : 0;
    } else {
        // exclusive prefix sum over 4096 cell counts (1024 threads x 4)
        __shared__ int sW[32];
        __shared__ int sE[32];
        const int t = threadIdx.x, lane = t & 31, wid = t >> 5;
        int v0 = g_cellCount[4*t+0];
        int v1 = g_cellCount[4*t+1];
        int v2 = g_cellCount[4*t+2];
        int v3 = g_cellCount[4*t+3];
        int s  = v0 + v1 + v2 + v3;
        int inc = s;
        #pragma unroll
        for (int off = 1; off < 32; off <<= 1){
            int y = __shfl_up_sync(0xFFFFFFFFu, inc, off);
            if (lane >= off) inc += y;
        }
        if (lane == 31) sW[wid] = inc;
        __syncthreads();
        if (wid == 0){
            int w = sW[lane];
            int i2 = w;
            #pragma unroll
            for (int off = 1; off < 32; off <<= 1){
                int y = __shfl_up_sync(0xFFFFFFFFu, i2, off);
                if (lane >= off) i2 += y;
            }
            sE[lane] = i2 - w;
        }
        __syncthreads();
        int run = sE[wid] + (inc - s);
        g_cellStart[4*t+0] = run;  g_cursor[4*t+0] = run;  run += v0;
        g_cellStart[4*t+1] = run;  g_cursor[4*t+1] = run;  run += v1;
        g_cellStart[4*t+2] = run;  g_cursor[4*t+2] = run;  run += v2;
        g_cellStart[4*t+3] = run;  g_cursor[4*t+3] = run;  run += v3;
        if (t == 1023) g_cellStart[NCELL] = run;
    }
}

// ---------------- node 3: fill sorted table ----------------
__global__ void __launch_bounds__(256) k_fill(const float* __restrict__ mem_pts){
    int i = blockIdx.x * 256 + threadIdx.x;
    if (i >= NMEM) return;
    float x = mem_pts[i*3+0], y = mem_pts[i*3+1], z = mem_pts[i*3+2];
    int c = (cellOf(z)*GD + cellOf(y))*GD + cellOf(x);
    int slot = atomicAdd(&g_cursor[c], 1);
    g_tbl[slot] = make_float4(x, y, z, __int_as_float(i));
}

// ---------------- node 4: grid NN query (warp per point) ----------------
__device__ __forceinline__ unsigned long long scanSeg(
        int s, int e, int lane, float px, float py, float pz,
        unsigned long long best){
    for (int j = s + lane; j < e; j += 32){
        float4 q = g_tbl[j];
        float dx = px - q.x, dy = py - q.y, dz = pz - q.z;
        float d2 = __fmaf_rn(dx, dx, __fmaf_rn(dy, dy, __fmul_rn(dz, dz)));
        unsigned long long key = ((unsigned long long)__float_as_uint(d2) << 32)
                               | (unsigned)__float_as_int(q.w);
        best = min(best, key);
    }
    return best;
}

__global__ void __launch_bounds__(256) k_nn(){
    const int lane = threadIdx.x & 31;
    const int p    = blockIdx.x * 8 + (threadIdx.x >> 5);
    const float px = g_world[p*3+0];
    const float py = g_world[p*3+1];
    const float pz = g_world[p*3+2];
    const int cx = cellOf(px), cy = cellOf(py), cz = cellOf(pz);

    unsigned long long best = ~0ULL;
    int R = 1;
    while (true){
        const int x0 = max(cx-R, 0), x1 = min(cx+R, GD-1);
        const int y0 = max(cy-R, 0), y1 = min(cy+R, GD-1);
        const int z0 = max(cz-R, 0), z1 = min(cz+R, GD-1);
        if (R == 1){
            for (int z = z0; z <= z1; z++)
                for (int y = y0; y <= y1; y++){
                    int c0 = (z*GD + y)*GD + x0;
                    int s  = g_cellStart[c0];
                    int e  = g_cellStart[c0 + (x1-x0) + 1];
                    best = scanSeg(s, e, lane, px, py, pz, best);
                }
        } else {
            for (int z = z0; z <= z1; z++)
                for (int y = y0; y <= y1; y++){
                    bool full = (z == cz-R) || (z == cz+R) || (y == cy-R) || (y == cy+R);
                    if (full){
                        int c0 = (z*GD + y)*GD + x0;
                        best = scanSeg(g_cellStart[c0], g_cellStart[c0 + (x1-x0) + 1],
                                       lane, px, py, pz, best);
                    } else {
                        int xl = cx-R, xr = cx+R;
                        if (xl >= 0){
                            int c = (z*GD + y)*GD + xl;
                            best = scanSeg(g_cellStart[c], g_cellStart[c+1],
                                           lane, px, py, pz, best);
                        }
                        if (xr <= GD-1){
                            int c = (z*GD + y)*GD + xr;
                            best = scanSeg(g_cellStart[c], g_cellStart[c+1],
                                           lane, px, py, pz, best);
                        }
                    }
                }
        }
        #pragma unroll
        for (int off = 16; off > 0; off >>= 1)
            best = min(best, __shfl_xor_sync(0xFFFFFFFFu, best, off));

        float bd2 = __uint_as_float((unsigned)(best >> 32));
        // conservative lower bound on any unexamined cell
        float lb = FLT_MAX;
        if (x0 > 0)     lb = fminf(lb, px - (OX + (float)x0*CS));
        if (x1 < GD-1)  lb = fminf(lb, (OX + (float)(x1+1)*CS) - px);
        if (y0 > 0)     lb = fminf(lb, py - (OX + (float)y0*CS));
        if (y1 < GD-1)  lb = fminf(lb, (OX + (float)(y1+1)*CS) - py);
        if (z0 > 0)     lb = fminf(lb, pz - (OX + (float)z0*CS));
        if (z1 < GD-1)  lb = fminf(lb, (OX + (float)(z1+1)*CS) - pz);
        if (lb == FLT_MAX) break;            // grid fully covered
        lb = fmaxf(lb, 0.0f);
        if (lb*lb > bd2) break;              // nothing closer can exist
        R++;
        if (R > 2*GD) break;                 // safety
    }
    if (lane == 0) g_bestKey[p] = best;
}

// ---------------- node 5: decide + scan slots + winners ----------------
__global__ void __launch_bounds__(1024) k_decide(const int* __restrict__ next_ptr){
    __shared__ int sWarp[32];
    __shared__ int sExc[32];
    __shared__ int sV[32];
    __shared__ int sM[32];
    const int t = threadIdx.x, lane = t & 31, wid = t >> 5;

    int u4[4], idx4[4];
    int usum = 0, vsum = 0, msum = 0;
    #pragma unroll
    for (int i = 0; i < 4; i++){
        int p = t*4 + i;
        unsigned long long key = g_bestKey[p];
        int idx = (int)(unsigned)(key & 0xFFFFFFFFull);
        float dmin = __uint_as_float((unsigned)(key >> 32));
        int v = g_valid[p];
        int m = (dmin < THR2) && v;
        int u = v && !m;
        g_flag[p] = m ? 2 : (u ? 1 : 0);
        u4[i] = u; idx4[i] = idx;
        usum += u; vsum += v; msum += m;
    }

    int inc = usum;
    #pragma unroll
    for (int off = 1; off < 32; off <<= 1){
        int y = __shfl_up_sync(0xFFFFFFFFu, inc, off);
        if (lane >= off) inc += y;
    }
    if (lane == 31) sWarp[wid] = inc;
    __syncthreads();
    if (wid == 0){
        int v = sWarp[lane];
        int inc2 = v;
        #pragma unroll
        for (int off = 1; off < 32; off <<= 1){
            int y = __shfl_up_sync(0xFFFFFFFFu, inc2, off);
            if (lane >= off) inc2 += y;
        }
        sExc[lane] = inc2 - v;
    }
    __syncthreads();
    int base = sExc[wid] + (inc - usum);
    int np = next_ptr[0];

    int run = base;
    #pragma unroll
    for (int i = 0; i < 4; i++){
        int p = t*4 + i;
        int w;
        if (u4[i]){ w = (np + run) % NMEM; run++; }
        else      { w = idx4[i]; }
        g_widx[p] = w;
        atomicMax(&g_winner[w], p + 1);
    }

    #pragma unroll
    for (int off = 16; off > 0; off >>= 1){
        vsum += __shfl_xor_sync(0xFFFFFFFFu, vsum, off);
        msum += __shfl_xor_sync(0xFFFFFFFFu, msum, off);
    }
    if (lane == 0){ sV[wid] = vsum; sM[wid] = msum; }
    __syncthreads();
    if (wid == 0){
        int a = sV[lane], b = sM[lane];
        #pragma unroll
        for (int off = 16; off > 0; off >>= 1){
            a += __shfl_xor_sync(0xFFFFFFFFu, a, off);
            b += __shfl_xor_sync(0xFFFFFFFFu, b, off);
        }
        if (lane == 0){ g_nvalid = a; g_nmatch = b; }
    }
}

// ---------------- node 6: fused patch (winner rows) + loss ----------------
__global__ void __launch_bounds__(256) k_patchloss(const float* __restrict__ desc,
                                                   const float* __restrict__ mem_desc,
                                                   float* __restrict__ out){
    __shared__ float ws[8];
    const int wid  = threadIdx.x >> 5;
    const int lane = threadIdx.x & 31;
    const int p    = blockIdx.x * 8 + wid;

    float* opts  = out + 2;
    float* odesc = out + 2 + NMEM*3;

    int f = g_flag[p];
    int r = g_widx[p];
    bool winner = (g_winner[r] == p + 1);
    float c = 0.0f;

    if (f != 0){
        const float4* A = (const float4*)(desc + (size_t)p * DDIM);
        float4 a0 = A[lane], a1 = A[lane+32];
        float na = a0.x*a0.x + a0.y*a0.y + a0.z*a0.z + a0.w*a0.w
                 + a1.x*a1.x + a1.y*a1.y + a1.z*a1.z + a1.w*a1.w;
        if (f == 2){
            const float4* B = (const float4*)(mem_desc + (size_t)r * DDIM);
            float4 b0 = B[lane], b1 = B[lane+32];
            float nb = b0.x*b0.x + b0.y*b0.y + b0.z*b0.z + b0.w*b0.w
                     + b1.x*b1.x + b1.y*b1.y + b1.z*b1.z + b1.w*b1.w;
            float dt = a0.x*b0.x + a0.y*b0.y + a0.z*b0.z + a0.w*b0.w
                     + a1.x*b1.x + a1.y*b1.y + a1.z*b1.z + a1.w*b1.w;
            #pragma unroll
            for (int o = 16; o > 0; o >>= 1){
                na += __shfl_xor_sync(0xFFFFFFFFu, na, o);
                nb += __shfl_xor_sync(0xFFFFFFFFu, nb, o);
                dt += __shfl_xor_sync(0xFFFFFFFFu, dt, o);
            }
            float n1 = fmaxf(sqrtf(na), EPSF);
            float n2 = fmaxf(sqrtf(nb), EPSF);
            c = dt / (n1 * n2);
            if (winner){
                float4 u0, u1;
                u0.x = a0.x*0.5f + b0.x*0.5f;  u0.y = a0.y*0.5f + b0.y*0.5f;
                u0.z = a0.z*0.5f + b0.z*0.5f;  u0.w = a0.w*0.5f + b0.w*0.5f;
                u1.x = a1.x*0.5f + b1.x*0.5f;  u1.y = a1.y*0.5f + b1.y*0.5f;
                u1.z = a1.z*0.5f + b1.z*0.5f;  u1.w = a1.w*0.5f + b1.w*0.5f;
                float ss = u0.x*u0.x + u0.y*u0.y + u0.z*u0.z + u0.w*u0.w
                         + u1.x*u1.x + u1.y*u1.y + u1.z*u1.z + u1.w*u1.w;
                #pragma unroll
                for (int o = 16; o > 0; o >>= 1)
                    ss += __shfl_xor_sync(0xFFFFFFFFu, ss, o);
                float inv = 1.0f / (sqrtf(ss) + EPSF);
                float2* drow = (float2*)(odesc + (size_t)r * DDIM);
                drow[2*lane + 0]      = make_float2(u0.x*inv, u0.y*inv);
                drow[2*lane + 1]      = make_float2(u0.z*inv, u0.w*inv);
                drow[2*(lane+32) + 0] = make_float2(u1.x*inv, u1.y*inv);
                drow[2*(lane+32) + 1] = make_float2(u1.z*inv, u1.w*inv);
            }
        } else {
            #pragma unroll
            for (int o = 16; o > 0; o >>= 1)
                na += __shfl_xor_sync(0xFFFFFFFFu, na, o);
            float n1 = fmaxf(sqrtf(na), EPSF);
            c = na / (n1 * n1);
            if (winner){
                if (lane < 3) opts[r*3 + lane] = g_world[p*3 + lane];
                float2* drow = (float2*)(odesc + (size_t)r * DDIM);
                drow[2*lane + 0]      = make_float2(a0.x, a0.y);
                drow[2*lane + 1]      = make_float2(a0.z, a0.w);
                drow[2*(lane+32) + 0] = make_float2(a1.x, a1.y);
                drow[2*(lane+32) + 1] = make_float2(a1.z, a1.w);
            }
        }
    }
    // invalid winner: row keeps the bulk-copied old value -> nothing to do

    if (lane == 0) ws[wid] = c;
    __syncthreads();
    if (threadIdx.x == 0){
        float s = 0.0f;
        #pragma unroll
        for (int i = 0; i < 8; i++) s += ws[i];
        g_partial[blockIdx.x] = s;
    }
}

// ---------------- node 7: finalize + state restore ----------------
__global__ void __launch_bounds__(512) k_final(float* __restrict__ out){
    __shared__ float s[512];
    const int t = threadIdx.x;
    s[t] = g_partial[t];
    __syncthreads();
    #pragma unroll
    for (int st = 256; st > 0; st >>= 1){
        if (t < st) s[t] += s[t + st];
        __syncthreads();
    }
    if (t == 0){
        int nv = g_nvalid; if (nv < 1) nv = 1;
        out[0] = 1.0f - s[0] / (float)nv;
        out[1] = (float)g_nmatch;
    }
    // restore mutable scratch for the next graph replay
    for (int i = t; i < P_TOT; i += 512)
        g_winner[g_widx[i]] = 0;
    for (int i = t; i < NCELL; i += 512)
        g_cellCount[i] = 0;
}

// ---------------- launch ----------------
extern "C" void kernel_launch(void* const* d_in, const int* in_sizes, int n_in,
                              void* d_out, int out_size) {
    const float* points   = (const float*)d_in[0];
    const float* depth    = (const float*)d_in[1];
    const float* pose     = (const float*)d_in[2];
    const float* Kmat     = (const float*)d_in[3];
    const float* desc     = (const float*)d_in[4];
    const float* mem_pts  = (const float*)d_in[5];
    const float* mem_desc = (const float*)d_in[6];
    const int*   next_ptr = (const int*)d_in[7];
    float* out = (float*)d_out;

    k_prep<<<COPY_BLOCKS + CNT_BLOCKS, 256>>>(mem_pts, mem_desc, out);
    k_pix_scan<<<BATCH + 1, 1024>>>(points, depth, pose, Kmat);
    k_fill<<<(NMEM + 255)/256, 256>>>(mem_pts);
    k_nn<<<P_TOT/8, 256>>>();
    k_decide<<<1, 1024>>>(next_ptr);
    k_patchloss<<<PL_BLOCKS, 256>>>(desc, mem_desc, out);
    k_final<<<1, 512>>>(out);
}

// round 6
// speedup vs baseline: 2.4675x; 1.1109x over previous
#include <cuda_runtime.h>
#include <cfloat>
#include <math.h>

#define BATCH 8
#define MPTS 512
#define P_TOT (BATCH*MPTS)        // 4096
#define DDIM 256
#define HH 480
#define WW 640
#define NMEM 50000
#define THR2 0.01f
#define EPSF 1e-8f

// spatial grid
#define GD 16                     // 16^3 = 4096 cells
#define NCELL (GD*GD*GD)
#define OX (-8.0f)
#define CS 1.0f

#define COPY_BLOCKS 1664
#define CNT_BLOCKS 224
#define CNT_THREADS (CNT_BLOCKS*256)
#define PL_BLOCKS 512             // patch+loss: 8 warps/block, warp per point

// ---- scratch (device globals; allocation-guard safe) ----
__device__ float               g_world[P_TOT*3];
__device__ int                 g_valid[P_TOT];
__device__ unsigned long long  g_bestKey[P_TOT];
__device__ int                 g_flag[P_TOT];     // 0 invalid, 1 unmatched, 2 matched
__device__ int                 g_widx[P_TOT];
__device__ int                 g_winner[NMEM];    // p+1; 0 = none (restored by k_final)
__device__ float               g_partial[PL_BLOCKS];
__device__ int                 g_nvalid;
__device__ int                 g_nmatch;
__device__ int                 g_cellCount[NCELL];      // zeroed statically + by k_final
__device__ int                 g_cellStart[NCELL+1];
__device__ int                 g_cursor[NCELL];
__device__ float4              g_tbl[NMEM];             // {x,y,z, idx-as-float-bits}

// ---------------- helpers ----------------
__device__ __forceinline__ int cellOf(float x){
    int c = (int)floorf((x - OX) * (1.0f/CS));
    return min(max(c, 0), GD-1);
}

// ---------------- node 1: bulk copy + histogram ----------------
__global__ void __launch_bounds__(256) k_prep(const float* __restrict__ mem_pts,
                                              const float* __restrict__ mem_desc,
                                              float* __restrict__ out){
    if (blockIdx.x < COPY_BLOCKS){
        // stream mem_desc (51.2 MB) -> out desc region (8B-aligned dst)
        int gid = blockIdx.x * 256 + threadIdx.x;
        const float4* s = (const float4*)mem_desc;
        float2* d = (float2*)(out + 2 + NMEM*3);
        const int n4 = NMEM*DDIM/4;
        for (int i = gid; i < n4; i += COPY_BLOCKS*256){
            float4 v = __ldcs(&s[i]);
            __stcs(&d[2*i+0], make_float2(v.x, v.y));
            __stcs(&d[2*i+1], make_float2(v.z, v.w));
        }
    } else {
        int k = (blockIdx.x - COPY_BLOCKS) * 256 + threadIdx.x;
        // copy mem_pts (600 KB)
        const float2* s2 = (const float2*)mem_pts;
        float2* d2 = (float2*)(out + 2);
        for (int j = k; j < NMEM*3/2; j += CNT_THREADS) d2[j] = __ldcs(&s2[j]);
        // cell histogram
        for (int i = k; i < NMEM; i += CNT_THREADS){
            int cx = cellOf(mem_pts[i*3+0]);
            int cy = cellOf(mem_pts[i*3+1]);
            int cz = cellOf(mem_pts[i*3+2]);
            atomicAdd(&g_cellCount[(cz*GD + cy)*GD + cx], 1);
        }
    }
}

// ---------------- node 2: pix2world (blocks 0-7) + cell scan (block 8) -----
__global__ void __launch_bounds__(1024) k_pix_scan(
        const float* __restrict__ pts2, const float* __restrict__ depth,
        const float* __restrict__ pose, const float* __restrict__ Kmat){
    if (blockIdx.x < BATCH){
        int bb = blockIdx.x;
        int m  = threadIdx.x;
        __shared__ float Ki[9];
        __shared__ float Rt[12];
        if (m == 0){
            const float* K = Kmat + bb*9;
            float k00=K[0],k01=K[1],k02=K[2],k10=K[3],k11=K[4],k12=K[5],k20=K[6],k21=K[7],k22=K[8];
            float c00 =  (k11*k22 - k12*k21);
            float c01 = -(k10*k22 - k12*k20);
            float c02 =  (k10*k21 - k11*k20);
            float det = k00*c00 + k01*c01 + k02*c02;
            float inv = 1.0f/det;
            Ki[0]= c00*inv;  Ki[1]=-(k01*k22-k02*k21)*inv;  Ki[2]= (k01*k12-k02*k11)*inv;
            Ki[3]= c01*inv;  Ki[4]= (k00*k22-k02*k20)*inv;  Ki[5]=-(k00*k12-k02*k10)*inv;
            Ki[6]= c02*inv;  Ki[7]=-(k00*k21-k01*k20)*inv;  Ki[8]= (k00*k11-k01*k10)*inv;
        }
        if (m < 12) Rt[m] = pose[bb*12 + m];
        __syncthreads();
        if (m >= MPTS) return;

        int p = bb*MPTS + m;
        float u = pts2[p*2+0];
        float v = pts2[p*2+1];
        float uc = fminf(fmaxf(u, 0.0f), 638.999f);
        float vc = fminf(fmaxf(v, 0.0f), 478.999f);
        float u0 = floorf(uc), v0 = floorf(vc);
        float du = uc - u0,   dv = vc - v0;
        int iu = (int)u0, iv = (int)v0;
        const float* dp = depth + (size_t)bb*HH*WW;
        float d00 = dp[iv*WW + iu],       d01 = dp[iv*WW + iu + 1];
        float d10 = dp[(iv+1)*WW + iu],   d11 = dp[(iv+1)*WW + iu + 1];
        float d = d00*(1.0f-du)*(1.0f-dv) + d01*du*(1.0f-dv)
                + d10*(1.0f-du)*dv        + d11*du*dv;
        float cx = (Ki[0]*u + Ki[1]*v + Ki[2]) * d;
        float cy = (Ki[3]*u + Ki[4]*v + Ki[5]) * d;
        float cz = (Ki[6]*u + Ki[7]*v + Ki[8]) * d;
        float wx = Rt[0]*cx + Rt[1]*cy + Rt[2]*cz  + Rt[3];
        float wy = Rt[4]*cx + Rt[5]*cy + Rt[6]*cz  + Rt[7];
        float wz = Rt[8]*cx + Rt[9]*cy + Rt[10]*cz + Rt[11];
        bool vld = (d > 0.0f) && isfinite(wx) && isfinite(wy) && isfinite(wz);
        g_world[p*3+0] = vld ? wx : 1e6f;
        g_world[p*3+1] = vld ? wy : 1e6f;
        g_world[p*3+2] = vld ? wz : 1e6f;
        g_valid[p]   = vld ? 1 : 0;
    } else {
        // exclusive prefix sum over 4096 cell counts (1024 threads x 4)
        __shared__ int sW[32];
        __shared__ int sE[32];
        const int t = threadIdx.x, lane = t & 31, wid = t >> 5;
        int v0 = g_cellCount[4*t+0];
        int v1 = g_cellCount[4*t+1];
        int v2 = g_cellCount[4*t+2];
        int v3 = g_cellCount[4*t+3];
        int s  = v0 + v1 + v2 + v3;
        int inc = s;
        #pragma unroll
        for (int off = 1; off < 32; off <<= 1){
            int y = __shfl_up_sync(0xFFFFFFFFu, inc, off);
            if (lane >= off) inc += y;
        }
        if (lane == 31) sW[wid] = inc;
        __syncthreads();
        if (wid == 0){
            int w = sW[lane];
            int i2 = w;
            #pragma unroll
            for (int off = 1; off < 32; off <<= 1){
                int y = __shfl_up_sync(0xFFFFFFFFu, i2, off);
                if (lane >= off) i2 += y;
            }
            sE[lane] = i2 - w;
        }
        __syncthreads();
        int run = sE[wid] + (inc - s);
        g_cellStart[4*t+0] = run;  g_cursor[4*t+0] = run;  run += v0;
        g_cellStart[4*t+1] = run;  g_cursor[4*t+1] = run;  run += v1;
        g_cellStart[4*t+2] = run;  g_cursor[4*t+2] = run;  run += v2;
        g_cellStart[4*t+3] = run;  g_cursor[4*t+3] = run;  run += v3;
        if (t == 1023) g_cellStart[NCELL] = run;
    }
}

// ---------------- node 3: fill sorted table ----------------
__global__ void __launch_bounds__(256) k_fill(const float* __restrict__ mem_pts){
    int i = blockIdx.x * 256 + threadIdx.x;
    if (i >= NMEM) return;
    float x = mem_pts[i*3+0], y = mem_pts[i*3+1], z = mem_pts[i*3+2];
    int c = (cellOf(z)*GD + cellOf(y))*GD + cellOf(x);
    int slot = atomicAdd(&g_cursor[c], 1);
    g_tbl[slot] = make_float4(x, y, z, __int_as_float(i));
}

// ---------------- node 4: grid NN query (warp per point, flattened) --------
__device__ __forceinline__ unsigned long long scanSeg(
        int s, int e, int lane, float px, float py, float pz,
        unsigned long long best){
    for (int j = s + lane; j < e; j += 32){
        float4 q = g_tbl[j];
        float dx = px - q.x, dy = py - q.y, dz = pz - q.z;
        float d2 = __fmaf_rn(dx, dx, __fmaf_rn(dy, dy, __fmul_rn(dz, dz)));
        unsigned long long key = ((unsigned long long)__float_as_uint(d2) << 32)
                               | (unsigned)__float_as_int(q.w);
        best = min(best, key);
    }
    return best;
}

__global__ void __launch_bounds__(256) k_nn(){
    const int lane = threadIdx.x & 31;
    const int p    = blockIdx.x * 8 + (threadIdx.x >> 5);
    const float px = g_world[p*3+0];
    const float py = g_world[p*3+1];
    const float pz = g_world[p*3+2];
    const int cx = cellOf(px), cy = cellOf(py), cz = cellOf(pz);

    unsigned long long best = ~0ULL;

    // ---- R=1 box, flattened: 9 row segments loaded in parallel ----
    {
        const int x0 = max(cx-1, 0), x1 = min(cx+1, GD-1);
        const int xw = x1 - x0 + 1;
        int s = 0, len = 0;
        if (lane < 9){
            int y = cy + (lane % 3) - 1;
            int z = cz + (lane / 3) - 1;
            if (y >= 0 && y < GD && z >= 0 && z < GD){
                int c0 = (z*GD + y)*GD + x0;
                s   = g_cellStart[c0];
                len = g_cellStart[c0 + xw] - s;
            }
        }
        // exclusive scan of segment lengths
        int inc = len;
        #pragma unroll
        for (int o = 1; o < 32; o <<= 1){
            int y = __shfl_up_sync(0xFFFFFFFFu, inc, o);
            if (lane >= o) inc += y;
        }
        const int off = inc - len;               // exclusive prefix (valid lanes 0..8)
        const int T   = __shfl_sync(0xFFFFFFFFu, inc, 31);
        const int gb  = s - off;                 // tbl index = gb + flat_t

        // broadcast all 9 segment descriptors while the warp is CONVERGED
        int offA[9], gbA[9];
        #pragma unroll
        for (int r = 0; r < 9; r++){
            offA[r] = __shfl_sync(0xFFFFFFFFu, off, r);
            gbA[r]  = __shfl_sync(0xFFFFFFFFu, gb,  r);
        }

        // shuffle-free divergent loop
        for (int t = lane; t < T; t += 32){
            int seg = 0;
            #pragma unroll
            for (int r = 1; r < 9; r++)
                seg = (t >= offA[r]) ? r : seg;  // ties resolve past empty segments
            float4 q = g_tbl[gbA[seg] + t];
            float dx = px - q.x, dy = py - q.y, dz = pz - q.z;
            float d2 = __fmaf_rn(dx, dx, __fmaf_rn(dy, dy, __fmul_rn(dz, dz)));
            unsigned long long key = ((unsigned long long)__float_as_uint(d2) << 32)
                                   | (unsigned)__float_as_int(q.w);
            best = min(best, key);
        }
    }
    #pragma unroll
    for (int o = 16; o > 0; o >>= 1)
        best = min(best, __shfl_xor_sync(0xFFFFFFFFu, best, o));

    // ---- exact ring expansion (rare: only if box boundary could beat best) ----
    int R = 1;
    while (true){
        const int x0 = max(cx-R, 0), x1 = min(cx+R, GD-1);
        const int y0 = max(cy-R, 0), y1 = min(cy+R, GD-1);
        const int z0 = max(cz-R, 0), z1 = min(cz+R, GD-1);
        float bd2 = __uint_as_float((unsigned)(best >> 32));
        float lb = FLT_MAX;
        if (x0 > 0)     lb = fminf(lb, px - (OX + (float)x0*CS));
        if (x1 < GD-1)  lb = fminf(lb, (OX + (float)(x1+1)*CS) - px);
        if (y0 > 0)     lb = fminf(lb, py - (OX + (float)y0*CS));
        if (y1 < GD-1)  lb = fminf(lb, (OX + (float)(y1+1)*CS) - py);
        if (z0 > 0)     lb = fminf(lb, pz - (OX + (float)z0*CS));
        if (z1 < GD-1)  lb = fminf(lb, (OX + (float)(z1+1)*CS) - pz);
        if (lb == FLT_MAX) break;            // grid fully covered
        lb = fmaxf(lb, 0.0f);
        if (lb*lb > bd2) break;              // nothing closer can exist
        R++;
        if (R > 2*GD) break;                 // safety
        const int nx0 = max(cx-R, 0), nx1 = min(cx+R, GD-1);
        const int ny0 = max(cy-R, 0), ny1 = min(cy+R, GD-1);
        const int nz0 = max(cz-R, 0), nz1 = min(cz+R, GD-1);
        for (int z = nz0; z <= nz1; z++)
            for (int y = ny0; y <= ny1; y++){
                bool full = (z == cz-R) || (z == cz+R) || (y == cy-R) || (y == cy+R);
                if (full){
                    int c0 = (z*GD + y)*GD + nx0;
                    best = scanSeg(g_cellStart[c0], g_cellStart[c0 + (nx1-nx0) + 1],
                                   lane, px, py, pz, best);
                } else {
                    int xl = cx-R, xr = cx+R;
                    if (xl >= 0){
                        int c = (z*GD + y)*GD + xl;
                        best = scanSeg(g_cellStart[c], g_cellStart[c+1],
                                       lane, px, py, pz, best);
                    }
                    if (xr <= GD-1){
                        int c = (z*GD + y)*GD + xr;
                        best = scanSeg(g_cellStart[c], g_cellStart[c+1],
                                       lane, px, py, pz, best);
                    }
                }
            }
        #pragma unroll
        for (int o = 16; o > 0; o >>= 1)
            best = min(best, __shfl_xor_sync(0xFFFFFFFFu, best, o));
    }
    if (lane == 0) g_bestKey[p] = best;
}

// ---------------- node 5: decide + scan slots + winners ----------------
__global__ void __launch_bounds__(1024) k_decide(const int* __restrict__ next_ptr){
    __shared__ int sWarp[32];
    __shared__ int sExc[32];
    __shared__ int sV[32];
    __shared__ int sM[32];
    const int t = threadIdx.x, lane = t & 31, wid = t >> 5;

    int u4[4], idx4[4];
    int usum = 0, vsum = 0, msum = 0;
    #pragma unroll
    for (int i = 0; i < 4; i++){
        int p = t*4 + i;
        unsigned long long key = g_bestKey[p];
        int idx = (int)(unsigned)(key & 0xFFFFFFFFull);
        float dmin = __uint_as_float((unsigned)(key >> 32));
        int v = g_valid[p];
        int m = (dmin < THR2) && v;
        int u = v && !m;
        g_flag[p] = m ? 2 : (u ? 1 : 0);
        u4[i] = u; idx4[i] = idx;
        usum += u; vsum += v; msum += m;
    }

    int inc = usum;
    #pragma unroll
    for (int off = 1; off < 32; off <<= 1){
        int y = __shfl_up_sync(0xFFFFFFFFu, inc, off);
        if (lane >= off) inc += y;
    }
    if (lane == 31) sWarp[wid] = inc;
    __syncthreads();
    if (wid == 0){
        int v = sWarp[lane];
        int inc2 = v;
        #pragma unroll
        for (int off = 1; off < 32; off <<= 1){
            int y = __shfl_up_sync(0xFFFFFFFFu, inc2, off);
            if (lane >= off) inc2 += y;
        }
        sExc[lane] = inc2 - v;
    }
    __syncthreads();
    int base = sExc[wid] + (inc - usum);
    int np = next_ptr[0];

    int run = base;
    #pragma unroll
    for (int i = 0; i < 4; i++){
        int p = t*4 + i;
        int w;
        if (u4[i]){ w = (np + run) % NMEM; run++; }
        else      { w = idx4[i]; }
        g_widx[p] = w;
        atomicMax(&g_winner[w], p + 1);
    }

    #pragma unroll
    for (int off = 16; off > 0; off >>= 1){
        vsum += __shfl_xor_sync(0xFFFFFFFFu, vsum, off);
        msum += __shfl_xor_sync(0xFFFFFFFFu, msum, off);
    }
    if (lane == 0){ sV[wid] = vsum; sM[wid] = msum; }
    __syncthreads();
    if (wid == 0){
        int a = sV[lane], b = sM[lane];
        #pragma unroll
        for (int off = 16; off > 0; off >>= 1){
            a += __shfl_xor_sync(0xFFFFFFFFu, a, off);
            b += __shfl_xor_sync(0xFFFFFFFFu, b, off);
        }
        if (lane == 0){ g_nvalid = a; g_nmatch = b; }
    }
}

// ---------------- node 6: fused patch (winner rows) + loss ----------------
__global__ void __launch_bounds__(256) k_patchloss(const float* __restrict__ desc,
                                                   const float* __restrict__ mem_desc,
                                                   float* __restrict__ out){
    __shared__ float ws[8];
    const int wid  = threadIdx.x >> 5;
    const int lane = threadIdx.x & 31;
    const int p    = blockIdx.x * 8 + wid;

    float* opts  = out + 2;
    float* odesc = out + 2 + NMEM*3;

    int f = g_flag[p];
    int r = g_widx[p];
    bool winner = (g_winner[r] == p + 1);
    float c = 0.0f;

    if (f != 0){
        const float4* A = (const float4*)(desc + (size_t)p * DDIM);
        float4 a0 = A[lane], a1 = A[lane+32];
        float na = a0.x*a0.x + a0.y*a0.y + a0.z*a0.z + a0.w*a0.w
                 + a1.x*a1.x + a1.y*a1.y + a1.z*a1.z + a1.w*a1.w;
        if (f == 2){
            const float4* B = (const float4*)(mem_desc + (size_t)r * DDIM);
            float4 b0 = B[lane], b1 = B[lane+32];
            float nb = b0.x*b0.x + b0.y*b0.y + b0.z*b0.z + b0.w*b0.w
                     + b1.x*b1.x + b1.y*b1.y + b1.z*b1.z + b1.w*b1.w;
            float dt = a0.x*b0.x + a0.y*b0.y + a0.z*b0.z + a0.w*b0.w
                     + a1.x*b1.x + a1.y*b1.y + a1.z*b1.z + a1.w*b1.w;
            #pragma unroll
            for (int o = 16; o > 0; o >>= 1){
                na += __shfl_xor_sync(0xFFFFFFFFu, na, o);
                nb += __shfl_xor_sync(0xFFFFFFFFu, nb, o);
                dt += __shfl_xor_sync(0xFFFFFFFFu, dt, o);
            }
            float n1 = fmaxf(sqrtf(na), EPSF);
            float n2 = fmaxf(sqrtf(nb), EPSF);
            c = dt / (n1 * n2);
            if (winner){
                float4 u0, u1;
                u0.x = a0.x*0.5f + b0.x*0.5f;  u0.y = a0.y*0.5f + b0.y*0.5f;
                u0.z = a0.z*0.5f + b0.z*0.5f;  u0.w = a0.w*0.5f + b0.w*0.5f;
                u1.x = a1.x*0.5f + b1.x*0.5f;  u1.y = a1.y*0.5f + b1.y*0.5f;
                u1.z = a1.z*0.5f + b1.z*0.5f;  u1.w = a1.w*0.5f + b1.w*0.5f;
                float ss = u0.x*u0.x + u0.y*u0.y + u0.z*u0.z + u0.w*u0.w
                         + u1.x*u1.x + u1.y*u1.y + u1.z*u1.z + u1.w*u1.w;
                #pragma unroll
                for (int o = 16; o > 0; o >>= 1)
                    ss += __shfl_xor_sync(0xFFFFFFFFu, ss, o);
                float inv = 1.0f / (sqrtf(ss) + EPSF);
                float2* drow = (float2*)(odesc + (size_t)r * DDIM);
                drow[2*lane + 0]      = make_float2(u0.x*inv, u0.y*inv);
                drow[2*lane + 1]      = make_float2(u0.z*inv, u0.w*inv);
                drow[2*(lane+32) + 0] = make_float2(u1.x*inv, u1.y*inv);
                drow[2*(lane+32) + 1] = make_float2(u1.z*inv, u1.w*inv);
            }
        } else {
            #pragma unroll
            for (int o = 16; o > 0; o >>= 1)
                na += __shfl_xor_sync(0xFFFFFFFFu, na, o);
            float n1 = fmaxf(sqrtf(na), EPSF);
            c = na / (n1 * n1);
            if (winner){
                if (lane < 3) opts[r*3 + lane] = g_world[p*3 + lane];
                float2* drow = (float2*)(odesc + (size_t)r * DDIM);
                drow[2*lane + 0]      = make_float2(a0.x, a0.y);
                drow[2*lane + 1]      = make_float2(a0.z, a0.w);
                drow[2*(lane+32) + 0] = make_float2(a1.x, a1.y);
                drow[2*(lane+32) + 1] = make_float2(a1.z, a1.w);
            }
        }
    }
    // invalid winner: row keeps the bulk-copied old value -> nothing to do

    if (lane == 0) ws[wid] = c;
    __syncthreads();
    if (threadIdx.x == 0){
        float s = 0.0f;
        #pragma unroll
        for (int i = 0; i < 8; i++) s += ws[i];
        g_partial[blockIdx.x] = s;
    }
}

// ---------------- node 7: finalize + state restore ----------------
__global__ void __launch_bounds__(512) k_final(float* __restrict__ out){
    __shared__ float s[512];
    const int t = threadIdx.x;
    s[t] = g_partial[t];
    __syncthreads();
    #pragma unroll
    for (int st = 256; st > 0; st >>= 1){
        if (t < st) s[t] += s[t + st];
        __syncthreads();
    }
    if (t == 0){
        int nv = g_nvalid; if (nv < 1) nv = 1;
        out[0] = 1.0f - s[0] / (float)nv;
        out[1] = (float)g_nmatch;
    }
    // restore mutable scratch for the next graph replay
    for (int i = t; i < P_TOT; i += 512)
        g_winner[g_widx[i]] = 0;
    for (int i = t; i < NCELL; i += 512)
        g_cellCount[i] = 0;
}

// ---------------- launch ----------------
extern "C" void kernel_launch(void* const* d_in, const int* in_sizes, int n_in,
                              void* d_out, int out_size) {
    const float* points   = (const float*)d_in[0];
    const float* depth    = (const float*)d_in[1];
    const float* pose     = (const float*)d_in[2];
    const float* Kmat     = (const float*)d_in[3];
    const float* desc     = (const float*)d_in[4];
    const float* mem_pts  = (const float*)d_in[5];
    const float* mem_desc = (const float*)d_in[6];
    const int*   next_ptr = (const int*)d_in[7];
    float* out = (float*)d_out;

    k_prep<<<COPY_BLOCKS + CNT_BLOCKS, 256>>>(mem_pts, mem_desc, out);
    k_pix_scan<<<BATCH + 1, 1024>>>(points, depth, pose, Kmat);
    k_fill<<<(NMEM + 255)/256, 256>>>(mem_pts);
    k_nn<<<P_TOT/8, 256>>>();
    k_decide<<<1, 1024>>>(next_ptr);
    k_patchloss<<<PL_BLOCKS, 256>>>(desc, mem_desc, out);
    k_final<<<1, 512>>>(out);
}